// round 11
// baseline (speedup 1.0000x reference)
#include <cuda_runtime.h>

// Problem constants
constexpr int Tn = 1000, Dd = 64, Nn = 128, Bb = 1000;
constexpr size_t REGION4 = (size_t)Bb * Tn * Nn / 4;   // float4 per output region
constexpr int NCTA = 148;            // 1 producer CTA + 147 consumer CTAs
constexpr int TPB = 512;
constexpr int NWARP_CONS = 147 * (TPB / 32);           // 2352 consumer warps
constexpr int NTASK = 2 * Tn + Bb;                     // 2000 bcast + 1000 trace
constexpr unsigned SENT = 0x7fc00001u;                 // NaN payload sentinel

// KEY INSIGHT 1: reference broadcasts x_t across all B rows from identical zero
// state => all rows identical. Simulate ONCE; broadcast.
// KEY INSIGHT 2 (R11): sim and broadcast are each large; overlap them with a
// FENCE-FREE producer/consumer: consumers poll the data itself against a NaN
// sentinel (per-4B-element validity; no ordering needed), producer runs
// completely unperturbed.

__device__ float g_inp_cur[Tn * Nn];
__device__ float g_spk[Tn * Nn];
__device__ float g_memh[Tn * Nn];
__device__ float g_trc[Nn];

// ---------------------------------------------------------------------------
// Kernel A: input currents + sentinel-poison the staging buffers.
// ---------------------------------------------------------------------------
__global__ void inp_cur_kernel(const float* __restrict__ sig,
                               const float* __restrict__ w_in) {
    const int t = blockIdx.x, n = threadIdx.x;
    float acc = 0.f;
#pragma unroll
    for (int d = 0; d < Dd; ++d) acc += sig[t * Dd + d] * w_in[d * Nn + n];
    g_inp_cur[t * Nn + n] = acc;
    const float sv = __uint_as_float(SENT);
    g_spk[t * Nn + n] = sv;
    g_memh[t * Nn + n] = sv;
    if (t == 0) g_trc[n] = sv;
}

// ---------------------------------------------------------------------------
// Producer: 128-thread sim of one row (thread = neuron). R8-validated loop:
// update -> ballot -> parallel lane-compaction index lists (pad to x4 with
// idx 128 = zero W row) -> named barrier (128) -> packed uchar4 list walk.
// Plain stores to compact staging; NO fences anywhere.
// ---------------------------------------------------------------------------
__device__ void run_producer(float* __restrict__ sW) {
    __shared__ __align__(4) unsigned char sList[2][4][40];
    __shared__ __align__(4) unsigned char sCnt[2][4];

    const int n = threadIdx.x;               // 0..127
    const int warp = n >> 5, lane = n & 31;

    float syn = 0.f, mem = 0.f, refr = 0.f, rec = 0.f, trc = 0.f;
    const float* __restrict__ xin = g_inp_cur;
    const float* __restrict__ wp = sW + n;   // W[k][n] = wp[k*128]
    const unsigned lt = (lane == 0) ? 0u : (0xFFFFFFFFu >> (32 - lane));

    float x = xin[n];

    for (int t = 0; t < Tn; ++t) {
        const int tnn = (t + 1 < Tn) ? (t + 1) : t;
        const float xn = __ldg(&xin[tnn * Nn + n]);

        syn = syn * 0.8f + (x + rec);
        mem = mem * 0.9f + syn * 0.1f;
        mem = (refr > 0.f) ? 0.f : mem;
        refr = fmaxf(refr - 1.f, 0.f);
        const bool k = mem > 1.0f;
        const float s = k ? 1.f : 0.f;
        mem = k ? 0.f : mem;
        refr += s * 2.f;
        trc = trc * 0.95f + s;

        const unsigned mw = __ballot_sync(0xFFFFFFFFu, k);
        const int buf = t & 1;
        const int c = __popc(mw);
        if (k) sList[buf][warp][__popc(mw & lt)] = (unsigned char)(warp * 32 + lane);
        if (lane < 4) sList[buf][warp][c + lane] = 128;
        if (lane == 0) sCnt[buf][warp] = (unsigned char)c;

        g_spk[t * Nn + n] = s;       // plain stores; consumers validate per-elem
        g_memh[t * Nn + n] = mem;

        asm volatile("bar.sync 1, 128;" ::: "memory");

        const unsigned cnts = *reinterpret_cast<const unsigned*>(&sCnt[buf][0]);
        float accA = 0.f, accB = 0.f;
#pragma unroll
        for (int j = 0; j < 4; ++j) {
            const int cj = (cnts >> (8 * j)) & 0xFF;
            const unsigned* __restrict__ lst =
                reinterpret_cast<const unsigned*>(&sList[buf][j][0]);
            for (int i = 0; i < cj; i += 4) {
                const unsigned w4 = lst[i >> 2];
                accA += wp[(w4 & 0xFFu) * Nn];
                accB += wp[((w4 >> 8) & 0xFFu) * Nn];
                accA += wp[((w4 >> 16) & 0xFFu) * Nn];
                accB += wp[(w4 >> 24) * Nn];
            }
        }
        rec = rec * 0.95f + (accA + accB);
        x = xn;
    }
    g_trc[n] = trc;
}

// ---------------------------------------------------------------------------
// Consumer: one task = validate one compact 512B row (sentinel poll with
// backoff), then stream it to 1000 output rows. Trace tasks analogous.
// ---------------------------------------------------------------------------
__device__ __forceinline__ unsigned valid4(float4 v) {
    return (__float_as_uint(v.x) != SENT) & (__float_as_uint(v.y) != SENT) &
           (__float_as_uint(v.z) != SENT) & (__float_as_uint(v.w) != SENT);
}

__device__ float4 poll4(const float4* p) {
    float4 v = __ldcv(p);
    unsigned ok = valid4(v);
    unsigned ns = 1024;
    while (!__all_sync(0xFFFFFFFFu, ok)) {
        __nanosleep(ns);
        ns = (ns < 16384u) ? ns * 2 : 16384u;
        v = __ldcv(p);
        ok = valid4(v);
    }
    return v;
}

__device__ void run_consumer(int cw, float* __restrict__ out) {
    const int lane = threadIdx.x & 31;
    float4* __restrict__ out4 = reinterpret_cast<float4*>(out);

    for (int tau = cw; tau < NTASK; tau += NWARP_CONS) {
        if (tau < 2 * Tn) {
            const int t = tau >> 1;
            const int reg = tau & 1;
            const float4* src = reinterpret_cast<const float4*>(
                                    reg ? g_memh : g_spk) + t * 32 + lane;
            const float4 v = poll4(src);
            float4* dst = out4 + (size_t)reg * REGION4 + (size_t)t * 32 + lane;
#pragma unroll 8
            for (int b = 0; b < Bb; ++b)
                dst[(size_t)b * (Tn * Nn / 4)] = v;
        } else {
            const int b = tau - 2 * Tn;
            const float4 v = poll4(reinterpret_cast<const float4*>(g_trc) + lane);
            out4[2 * REGION4 + (size_t)b * 32 + lane] = v;
        }
    }
}

// ---------------------------------------------------------------------------
// Fused kernel: CTA0 = producer (128 active threads), CTAs 1..147 consumers.
// ---------------------------------------------------------------------------
__global__ __launch_bounds__(TPB, 1)
void fused_kernel(const float* __restrict__ Wrec, float* __restrict__ out) {
    extern __shared__ float sW[];   // 129*128 floats (row 128 = zeros)
    const int bid = blockIdx.x, tid = threadIdx.x;

    if (bid == 0) {
        for (int i = tid; i < (129 * Nn) / 4; i += TPB)
            reinterpret_cast<float4*>(sW)[i] =
                (i < (Nn * Nn) / 4) ? reinterpret_cast<const float4*>(Wrec)[i]
                                    : make_float4(0.f, 0.f, 0.f, 0.f);
        __syncthreads();
        if (tid < 128) run_producer(sW);
        return;  // threads 128..511 idle; producer SM stays quiet
    }
    run_consumer((bid - 1) * (TPB / 32) + (tid >> 5), out);
}

// ---------------------------------------------------------------------------
// Harness entry
// ---------------------------------------------------------------------------
extern "C" void kernel_launch(void* const* d_in, const int* in_sizes, int n_in,
                              void* d_out, int out_size) {
    const float* sig   = (const float*)d_in[0];  // (1000, 64)
    const float* w_in  = (const float*)d_in[1];  // (64, 128)
    const float* w_rec = (const float*)d_in[2];  // (128, 128)
    float* out = (float*)d_out;
    (void)in_sizes; (void)n_in; (void)out_size;

    const int smem = 129 * Nn * (int)sizeof(float);
    cudaFuncSetAttribute(fused_kernel,
                         cudaFuncAttributeMaxDynamicSharedMemorySize, smem);

    inp_cur_kernel<<<Tn, Nn>>>(sig, w_in);
    fused_kernel<<<NCTA, TPB, smem>>>(w_rec, out);
}

// round 12
// speedup vs baseline: 1.0099x; 1.0099x over previous
#include <cuda_runtime.h>

// Problem constants
constexpr int Tn = 1000, Dd = 64, Nn = 128, Bb = 1000;
constexpr int GRID = 148;            // one CTA per SM
constexpr int TPB = 512;             // 16 warps: 4 sim + 12 store-heavy
constexpr size_t REGION4 = (size_t)Bb * Tn * Nn / 4;   // float4 per region

// KEY INSIGHT 1: reference broadcasts x_t across all B rows from identical
// zero state => all B rows produce identical outputs.
// KEY INSIGHT 2 (R12): every prior design was bound by instructions/SMSP/step
// (either the sim duplicated per row, or 1000 stores duplicated per element
// in one thread). Minimal design: ONE sim per SM; its per-step result goes
// through 1KB of smem staging; 448 store threads each do exactly one
// LDS.128 + STG.128 per step for their pre-assigned (row, region, f4) slot.
// ~75 instr/SMSP/step -> the 1.03GB output write becomes the limiter.

__device__ float g_inp_cur[Tn * Nn];  // (T, N) input currents

// ---------------------------------------------------------------------------
// Kernel A: input currents (1000x64 @ 64x128). ~5us.
// ---------------------------------------------------------------------------
__global__ void inp_cur_kernel(const float* __restrict__ sig,
                               const float* __restrict__ w_in) {
    int t = blockIdx.x, n = threadIdx.x;
    float acc = 0.f;
#pragma unroll
    for (int d = 0; d < Dd; ++d) acc += sig[t * Dd + d] * w_in[d * Nn + n];
    g_inp_cur[t * Nn + n] = acc;
}

// ---------------------------------------------------------------------------
// Kernel B: per-SM sim + fan-out store.
//   Phase 1 (threads 0-127, neuron n = tid): update -> ballot -> STS masks +
//     STS s/mem staging (double-buffered by t&1) -> prefetch x_{t+1}.
//   Barrier (one per step).
//   Phase 2: sim threads read masks, sparse-walk W (smem), update rec;
//     store threads (tid>=64, 448 tasks) copy staging -> their (row, region,
//     f4) slot in global: 1 LDS.128 + 1 STG.128 + ptr bump.
//   Rows of CTA b: { b + 148*i } (7 rows for b<112, else 6).
// ---------------------------------------------------------------------------
__global__ __launch_bounds__(TPB, 1)
void sim_kernel(const float* __restrict__ Wrec, float* __restrict__ out) {
    extern __shared__ float sW[];                 // 128*128 = 64KB
    __shared__ __align__(16) float4 stg[2][2][Nn / 4];  // [buf][region][f4]
    __shared__ __align__(16) unsigned smask[2][4];      // [buf][warp]

    const int tid = threadIdx.x;
    const int bid = blockIdx.x;

    // Cooperative load of W
    for (int i = tid; i < (Nn * Nn) / 4; i += TPB)
        reinterpret_cast<float4*>(sW)[i] =
            reinterpret_cast<const float4*>(Wrec)[i];
    __syncthreads();

    const bool isSim = tid < Nn;
    const int n = tid & (Nn - 1);
    const int warp = tid >> 5;
    const int lane = tid & 31;

    // Sim state
    float syn = 0.f, mem = 0.f, refr = 0.f, rec = 0.f, trc = 0.f, x = 0.f;
    const float* __restrict__ xin = g_inp_cur;
    const float* __restrict__ wp = sW + n;        // W[k][n] = wp[k*128]
    if (isSim) x = xin[n];

    // Store-task setup: tau in [0,448): f4 = tau&31, rr = tau>>5 in [0,14):
    // region = rr&1, row_i = rr>>1 in [0,7), row = bid + 148*row_i.
    const int tau = tid - 64;
    bool sValid = false;
    float4* dst = nullptr;
    const float4* srcA = nullptr;  // buf 0
    const float4* srcB = nullptr;  // buf 1
    int f4 = 0, region = 0, row = Bb;
    if (tau >= 0) {
        f4 = tau & 31;
        const int rr = tau >> 5;
        region = rr & 1;
        row = bid + GRID * (rr >> 1);
        if (row < Bb) {
            sValid = true;
            dst = reinterpret_cast<float4*>(out) + (size_t)region * REGION4 +
                  (size_t)row * (Tn * Nn / 4) + f4;
            srcA = &stg[0][region][f4];
            srcB = &stg[1][region][f4];
        }
    }

    for (int t = 0; t < Tn; ++t) {
        const int buf = t & 1;

        if (isSim) {
            const int tnn = (t + 1 < Tn) ? (t + 1) : t;
            const float xn = __ldg(&xin[tnn * Nn + n]);

            // ---- neuron update (order matches reference) ----
            syn = syn * 0.8f + (x + rec);
            mem = mem * 0.9f + syn * 0.1f;
            mem = (refr > 0.f) ? 0.f : mem;
            refr = fmaxf(refr - 1.f, 0.f);
            const bool k = mem > 1.0f;
            const float s = k ? 1.f : 0.f;
            mem = k ? 0.f : mem;
            refr += s * 2.f;
            trc = trc * 0.95f + s;

            const unsigned mw = __ballot_sync(0xFFFFFFFFu, k);
            if (lane == 0) smask[buf][warp] = mw;

            // Stage this step's outputs for the store threads
            reinterpret_cast<float*>(&stg[buf][0][0])[n] = s;
            reinterpret_cast<float*>(&stg[buf][1][0])[n] = mem;

            x = xn;
        }

        __syncthreads();   // the ONE barrier per step

        if (isSim) {
            // ---- sparse accumulate: rec = 0.95*rec + sum_spk W[src][n] ----
            const uint4 mm = *reinterpret_cast<const uint4*>(&smask[buf][0]);
            float acc = 0.f;
            unsigned m;
            m = mm.x; while (m) { int l = __ffs(m) - 1; m &= m - 1; acc += wp[l * Nn]; }
            m = mm.y; while (m) { int l = __ffs(m) - 1; m &= m - 1; acc += wp[(32 + l) * Nn]; }
            m = mm.z; while (m) { int l = __ffs(m) - 1; m &= m - 1; acc += wp[(64 + l) * Nn]; }
            m = mm.w; while (m) { int l = __ffs(m) - 1; m &= m - 1; acc += wp[(96 + l) * Nn]; }
            rec = rec * 0.95f + acc;
        }

        if (sValid) {
            *dst = buf ? *srcB : *srcA;   // LDS.128 + STG.128
            dst += Nn / 4;                // next timestep slot
        }
    }

    // ---- trace epilogue: stage trc, then fan out to this CTA's rows ----
    if (isSim) reinterpret_cast<float*>(&stg[0][0][0])[n] = trc;
    __syncthreads();
    if (sValid && region == 0) {
        reinterpret_cast<float4*>(out)[2 * REGION4 + (size_t)row * (Nn / 4) + f4] =
            stg[0][0][f4];
    }
}

// ---------------------------------------------------------------------------
// Harness entry
// ---------------------------------------------------------------------------
extern "C" void kernel_launch(void* const* d_in, const int* in_sizes, int n_in,
                              void* d_out, int out_size) {
    const float* sig   = (const float*)d_in[0];  // (1000, 64)
    const float* w_in  = (const float*)d_in[1];  // (64, 128)
    const float* w_rec = (const float*)d_in[2];  // (128, 128)
    float* out = (float*)d_out;
    (void)in_sizes; (void)n_in; (void)out_size;

    const int smem = Nn * Nn * (int)sizeof(float);   // 64 KB
    cudaFuncSetAttribute(sim_kernel,
                         cudaFuncAttributeMaxDynamicSharedMemorySize, smem);

    inp_cur_kernel<<<Tn, Nn>>>(sig, w_in);
    sim_kernel<<<GRID, TPB, smem>>>(w_rec, out);
}

// round 13
// speedup vs baseline: 1.1097x; 1.0988x over previous
#include <cuda_runtime.h>

// Problem constants
constexpr int Tn = 1000, Dd = 64, Nn = 128, Bb = 1000;
constexpr int GRID = 148;                 // one CTA per SM
constexpr int TPB = 128;                  // thread = neuron
constexpr int TILE = 64;                  // timesteps per TMA tile
constexpr int NTILE = (Tn + TILE - 1) / TILE;   // 16 (last tile = 40 steps)
constexpr size_t REGION = (size_t)Bb * Tn * Nn; // floats per output region

// KEY INSIGHT 1: reference broadcasts x_t across all B rows from identical
// zero state => all B rows produce identical outputs; each CTA re-runs the
// cheap one-row sim and OWNS 6-7 output rows.
// KEY INSIGHT 2 (R13): every prior design moved the 1.025GB output through
// per-thread STG (effective ~1.25 TB/s = the observed 820us floor). Move the
// entire output through TMA bulk stores issued from SMEM staging: zero
// global stores on the SM hot path; DMA overlaps the sim.

__device__ float g_inp_cur[Tn * Nn];  // (T, N) input currents

// ---------------------------------------------------------------------------
// Kernel A: input currents (1000x64 @ 64x128). ~5us.
// ---------------------------------------------------------------------------
__global__ void inp_cur_kernel(const float* __restrict__ sig,
                               const float* __restrict__ w_in) {
    int t = blockIdx.x, n = threadIdx.x;
    float acc = 0.f;
#pragma unroll
    for (int d = 0; d < Dd; ++d) acc += sig[t * Dd + d] * w_in[d * Nn + n];
    g_inp_cur[t * Nn + n] = acc;
}

// ---- PTX helpers -----------------------------------------------------------
__device__ __forceinline__ unsigned smem_u32(const void* p) {
    unsigned a;
    asm("{ .reg .u64 t; cvta.to.shared.u64 t, %1; cvt.u32.u64 %0, t; }"
        : "=r"(a) : "l"(p));
    return a;
}
__device__ __forceinline__ void bulk_store(void* gdst, unsigned ssrc,
                                           unsigned bytes) {
    asm volatile(
        "cp.async.bulk.global.shared::cta.bulk_group [%0], [%1], %2;"
        :: "l"(gdst), "r"(ssrc), "r"(bytes) : "memory");
}
__device__ __forceinline__ void bulk_commit() {
    asm volatile("cp.async.bulk.commit_group;" ::: "memory");
}
template <int N_>
__device__ __forceinline__ void bulk_wait() {
    asm volatile("cp.async.bulk.wait_group %0;" :: "n"(N_) : "memory");
}
__device__ __forceinline__ void fence_async_proxy() {
    asm volatile("fence.proxy.async.shared::cta;" ::: "memory");
}

// ---------------------------------------------------------------------------
// Kernel B: per-SM sim + TMA bulk output.
//   SMEM: W (129 rows; row 128 = zeros, pad target) + stg[2][2][TILE][Nn].
//   Per step: update -> ballot -> lane-compaction index lists -> STS staging
//     -> __syncthreads -> packed uchar4 list walk (R8-validated).
//   Per tile (64 steps): elected thread fences + issues 2*nrows bulk stores
//     (steps*512B each) + commit + wait_group(1); barrier; continue.
//   Rows of CTA b: { b + 148*i, i<7 } (7 rows for b<112, else 6).
// ---------------------------------------------------------------------------
__global__ __launch_bounds__(TPB, 1)
void sim_kernel(const float* __restrict__ Wrec, float* __restrict__ out) {
    extern __shared__ float smem_buf[];
    float* sW = smem_buf;                     // 129*128 floats
    float* stg = smem_buf + 129 * Nn;         // [2][2][TILE][Nn] floats
    __shared__ __align__(4) unsigned char sList[2][4][40];
    __shared__ __align__(4) unsigned char sCnt[2][4];

    const int n = threadIdx.x;                // neuron 0..127
    const int warp = n >> 5, lane = n & 31;
    const int bid = blockIdx.x;

    // Load W (+ zero pad row)
    for (int i = n; i < (129 * Nn) / 4; i += TPB)
        reinterpret_cast<float4*>(sW)[i] =
            (i < (Nn * Nn) / 4) ? reinterpret_cast<const float4*>(Wrec)[i]
                                : make_float4(0.f, 0.f, 0.f, 0.f);
    __syncthreads();

    float syn = 0.f, mem = 0.f, refr = 0.f, rec = 0.f, trc = 0.f;
    const float* __restrict__ xin = g_inp_cur;
    const float* __restrict__ wp = sW + n;    // W[k][n] = wp[k*128]
    const unsigned lt = (lane == 0) ? 0u : (0xFFFFFFFFu >> (32 - lane));
    float x = xin[n];

    const unsigned stg_base = smem_u32(stg);

    for (int tile = 0; tile < NTILE; ++tile) {
        const int t0 = tile * TILE;
        const int steps = (Tn - t0 < TILE) ? (Tn - t0) : TILE;
        float* __restrict__ sb = stg + (tile & 1) * (2 * TILE * Nn);

        for (int ts = 0; ts < steps; ++ts) {
            const int t = t0 + ts;
            const int tnn = (t + 1 < Tn) ? (t + 1) : t;
            const float xn = __ldg(&xin[tnn * Nn + n]);

            // ---- neuron update (order matches reference) ----
            syn = syn * 0.8f + (x + rec);
            mem = mem * 0.9f + syn * 0.1f;
            mem = (refr > 0.f) ? 0.f : mem;
            refr = fmaxf(refr - 1.f, 0.f);
            const bool k = mem > 1.0f;
            const float s = k ? 1.f : 0.f;
            mem = k ? 0.f : mem;
            refr += s * 2.f;
            trc = trc * 0.95f + s;

            // ---- parallel spike-index compaction ----
            const unsigned mw = __ballot_sync(0xFFFFFFFFu, k);
            const int buf = t & 1;
            const int c = __popc(mw);
            if (k) sList[buf][warp][__popc(mw & lt)] =
                       (unsigned char)(warp * 32 + lane);
            if (lane < 4) sList[buf][warp][c + lane] = 128;  // pad -> zero row
            if (lane == 0) sCnt[buf][warp] = (unsigned char)c;

            // ---- stage outputs (SMEM only; no global traffic) ----
            sb[ts * Nn + n] = s;
            sb[TILE * Nn + ts * Nn + n] = mem;

            __syncthreads();

            // ---- sparse accumulate via packed index lists ----
            const unsigned cnts =
                *reinterpret_cast<const unsigned*>(&sCnt[buf][0]);
            float accA = 0.f, accB = 0.f;
#pragma unroll
            for (int j = 0; j < 4; ++j) {
                const int cj = (cnts >> (8 * j)) & 0xFF;
                const unsigned* __restrict__ lst =
                    reinterpret_cast<const unsigned*>(&sList[buf][j][0]);
                for (int i = 0; i < cj; i += 4) {
                    const unsigned w4 = lst[i >> 2];
                    accA += wp[(w4 & 0xFFu) * Nn];
                    accB += wp[((w4 >> 8) & 0xFFu) * Nn];
                    accA += wp[((w4 >> 16) & 0xFFu) * Nn];
                    accB += wp[(w4 >> 24) * Nn];
                }
            }
            rec = rec * 0.95f + (accA + accB);
            x = xn;
        }

        // ---- TMA bulk stores for this tile (elected thread) ----
        // Last in-loop __syncthreads already made all staging STS visible.
        if (n == 0) {
            fence_async_proxy();
            const unsigned src0 = stg_base +
                (unsigned)((tile & 1) * (2 * TILE * Nn) * 4);
            const unsigned bytes = (unsigned)(steps * Nn * 4);
#pragma unroll
            for (int i = 0; i < 7; ++i) {
                const int row = bid + GRID * i;
                if (row < Bb) {
                    float* d0 = out + (size_t)row * Tn * Nn + (size_t)t0 * Nn;
                    bulk_store(d0, src0, bytes);                       // spikes
                    bulk_store(d0 + REGION, src0 + TILE * Nn * 4, bytes); // mem
                }
            }
            bulk_commit();
            bulk_wait<1>();   // buffer being filled next is free after this
        }
        __syncthreads();
    }

    // ---- drain DMA, then write trace for this CTA's rows ----
    if (n == 0) bulk_wait<0>();
    __syncthreads();
#pragma unroll
    for (int i = 0; i < 7; ++i) {
        const int row = bid + GRID * i;
        if (row < Bb) out[2 * REGION + (size_t)row * Nn + n] = trc;
    }
}

// ---------------------------------------------------------------------------
// Harness entry
// ---------------------------------------------------------------------------
extern "C" void kernel_launch(void* const* d_in, const int* in_sizes, int n_in,
                              void* d_out, int out_size) {
    const float* sig   = (const float*)d_in[0];  // (1000, 64)
    const float* w_in  = (const float*)d_in[1];  // (64, 128)
    const float* w_rec = (const float*)d_in[2];  // (128, 128)
    float* out = (float*)d_out;
    (void)in_sizes; (void)n_in; (void)out_size;

    // SMEM: 129*128 W + 2*2*64*128 staging = 66048 + 131072 = 197120 B
    const int smem = (129 * Nn + 2 * 2 * TILE * Nn) * (int)sizeof(float);
    cudaFuncSetAttribute(sim_kernel,
                         cudaFuncAttributeMaxDynamicSharedMemorySize, smem);

    inp_cur_kernel<<<Tn, Nn>>>(sig, w_in);
    sim_kernel<<<GRID, TPB, smem>>>(w_rec, out);
}

// round 14
// speedup vs baseline: 1.1857x; 1.0685x over previous
#include <cuda_runtime.h>

// Problem constants
constexpr int Tn = 1000, Dd = 64, Nn = 128, Bb = 1000;
constexpr size_t ROWF = (size_t)Tn * Nn;          // floats per row (128K = 512KB)
constexpr size_t REGION = (size_t)Bb * ROWF;      // floats per output region

// KEY INSIGHT 1: reference broadcasts x_t across all B rows from identical
// zero state => all B rows identical. Simulate once; broadcast.
// KEY INSIGHT 2 (R14): every prior round wrote the 1.025GB output in TIME
// order (512B chunks scattered across 1000 rows at 512KB stride) and all
// plateaued at ~1.1-1.27 TB/s. Because rows are identical, out[region][b] is
// a VERBATIM linear copy of the compact (T,N) buffer: broadcast = 2000
// independent contiguous 512KB memcpys (perfect DRAM streaming), src L2-hot.

__device__ float g_inp_cur[Tn * Nn];  // (T, N) input currents
__device__ float g_spk[Tn * Nn];      // compact spikes (T, N)
__device__ float g_memh[Tn * Nn];     // compact membrane (T, N)
__device__ float g_trc[Nn];           // final trace (N)

// ---------------------------------------------------------------------------
// Kernel A: input currents (1000x64 @ 64x128). ~5us.
// ---------------------------------------------------------------------------
__global__ void inp_cur_kernel(const float* __restrict__ sig,
                               const float* __restrict__ w_in) {
    int t = blockIdx.x, n = threadIdx.x;
    float acc = 0.f;
#pragma unroll
    for (int d = 0; d < Dd; ++d) acc += sig[t * Dd + d] * w_in[d * Nn + n];
    g_inp_cur[t * Nn + n] = acc;
}

// ---------------------------------------------------------------------------
// Kernel B: 128-thread sim of ONE row (thread = neuron). R8-validated loop:
//   update -> ballot -> parallel lane-compaction index lists (popc-prefix,
//   pad to x4 with idx 128 = zero W row) -> one __syncthreads -> packed
//   uchar4 list walk, dual FADD chains. Double-buffered; 1 barrier/step.
// ---------------------------------------------------------------------------
__global__ __launch_bounds__(128, 1)
void sim_kernel(const float* __restrict__ Wrec) {
    __shared__ float sW[129 * Nn];                    // row 128 = zeros (pad)
    __shared__ __align__(4) unsigned char sList[2][4][40];
    __shared__ __align__(4) unsigned char sCnt[2][4];

    const int n = threadIdx.x;
    const int warp = n >> 5, lane = n & 31;

    {
        float4* dst = reinterpret_cast<float4*>(sW);
        const float4* src = reinterpret_cast<const float4*>(Wrec);
        for (int i = n; i < (129 * Nn) / 4; i += 128)
            dst[i] = (i < (Nn * Nn) / 4) ? src[i] : make_float4(0.f, 0.f, 0.f, 0.f);
    }
    __syncthreads();

    float syn = 0.f, mem = 0.f, refr = 0.f, rec = 0.f, trc = 0.f;
    const float* __restrict__ xin = g_inp_cur;
    const float* __restrict__ wp = sW + n;            // W[k][n] = wp[k*128]
    const unsigned lt = (lane == 0) ? 0u : (0xFFFFFFFFu >> (32 - lane));

    float x = xin[n];

    for (int t = 0; t < Tn; ++t) {
        const int tnn = (t + 1 < Tn) ? (t + 1) : t;
        const float xn = __ldg(&xin[tnn * Nn + n]);

        // ---- neuron update (order matches reference) ----
        syn = syn * 0.8f + (x + rec);
        mem = mem * 0.9f + syn * 0.1f;
        mem = (refr > 0.f) ? 0.f : mem;
        refr = fmaxf(refr - 1.f, 0.f);
        const bool k = mem > 1.0f;
        const float s = k ? 1.f : 0.f;
        mem = k ? 0.f : mem;
        refr += s * 2.f;
        trc = trc * 0.95f + s;

        // ---- parallel spike-index compaction ----
        const unsigned mw = __ballot_sync(0xFFFFFFFFu, k);
        const int buf = t & 1;
        const int c = __popc(mw);
        if (k) sList[buf][warp][__popc(mw & lt)] = (unsigned char)(warp * 32 + lane);
        if (lane < 4) sList[buf][warp][c + lane] = 128;   // pad -> zero row
        if (lane == 0) sCnt[buf][warp] = (unsigned char)c;

        g_spk[t * Nn + n] = s;
        g_memh[t * Nn + n] = mem;

        __syncthreads();

        // ---- sparse accumulate: rec = 0.95*rec + sum_{spiking src} W[src][n]
        const unsigned cnts = *reinterpret_cast<const unsigned*>(&sCnt[buf][0]);
        float accA = 0.f, accB = 0.f;
#pragma unroll
        for (int j = 0; j < 4; ++j) {
            const int cj = (cnts >> (8 * j)) & 0xFF;
            const unsigned* __restrict__ lst =
                reinterpret_cast<const unsigned*>(&sList[buf][j][0]);
            for (int i = 0; i < cj; i += 4) {
                const unsigned w4 = lst[i >> 2];
                accA += wp[(w4 & 0xFFu) * Nn];
                accB += wp[((w4 >> 8) & 0xFFu) * Nn];
                accA += wp[((w4 >> 16) & 0xFFu) * Nn];
                accB += wp[(w4 >> 24) * Nn];
            }
        }
        rec = rec * 0.95f + (accA + accB);
        x = xn;
    }

    g_trc[n] = trc;
}

// ---------------------------------------------------------------------------
// Kernel C: DESTINATION-ORDERED broadcast. CTA c (0..1999):
//   region = c/1000, row = c%1000. out[region][row] is a verbatim linear
//   copy of the compact buffer: one contiguous 512KB memcpy per CTA,
//   perfectly coalesced, sequential addresses. Source stays L2-resident.
// ---------------------------------------------------------------------------
constexpr int CP_TPB = 256;
constexpr int CP_PER_THREAD = (int)(ROWF / 4 / CP_TPB);  // 125 float4

__global__ __launch_bounds__(CP_TPB, 8)
void bcast_kernel(float* __restrict__ out) {
    const int c = blockIdx.x;
    const int region = (c >= Bb) ? 1 : 0;
    const int row = c - region * Bb;
    const float4* __restrict__ src =
        reinterpret_cast<const float4*>(region ? g_memh : g_spk);
    float4* __restrict__ dst = reinterpret_cast<float4*>(out) +
        (size_t)region * (REGION / 4) + (size_t)row * (ROWF / 4);

    int i = threadIdx.x;
#pragma unroll 5
    for (int it = 0; it < CP_PER_THREAD; ++it, i += CP_TPB)
        __stcs(&dst[i], __ldg(&src[i]));
}

// ---------------------------------------------------------------------------
// Kernel D: broadcast trace (N) to (B, N). 512KB, ~4us.
// ---------------------------------------------------------------------------
__global__ void trace_kernel(float* __restrict__ out) {
    const int i = blockIdx.x * 256 + threadIdx.x;  // < B*N/4 = 32000
    const float4 v = reinterpret_cast<const float4*>(g_trc)[i & 31];
    __stcs(&reinterpret_cast<float4*>(out + 2 * REGION)[i], v);
}

// ---------------------------------------------------------------------------
// Harness entry
// ---------------------------------------------------------------------------
extern "C" void kernel_launch(void* const* d_in, const int* in_sizes, int n_in,
                              void* d_out, int out_size) {
    const float* sig   = (const float*)d_in[0];  // (1000, 64)
    const float* w_in  = (const float*)d_in[1];  // (64, 128)
    const float* w_rec = (const float*)d_in[2];  // (128, 128)
    float* out = (float*)d_out;
    (void)in_sizes; (void)n_in; (void)out_size;

    inp_cur_kernel<<<Tn, Nn>>>(sig, w_in);
    sim_kernel<<<1, 128>>>(w_rec);
    bcast_kernel<<<2 * Bb, CP_TPB>>>(out);
    trace_kernel<<<(Bb * Nn / 4) / 256, 256>>>(out);
}

// round 15
// speedup vs baseline: 1.2873x; 1.0857x over previous
#include <cuda_runtime.h>

// Problem constants (fixed shapes for this problem instance)
constexpr int Tn = 1000;   // timesteps
constexpr int Dd = 64;     // input dim
constexpr int Nn = 128;    // neurons
constexpr int Bb = 1000;   // batch rows
constexpr int ROWS_PER_CTA = 4;           // 8 warps per CTA, 2 warps per row
constexpr int THREADS = ROWS_PER_CTA * 2 * 32;  // 256

typedef unsigned long long ull;

// Model (validated over 14 rounds): output writes cap at ~1.25 TB/s on this
// setup regardless of pattern (STG scatter / fanout / TMA / contiguous), so
// the floor is ~805us and the winning design is the fully-fused kernel whose
// stores start at t=0 and issue densely, hiding all compute inside the write
// stream. This is the R2 champion with stores hoisted before the barrier so
// they drain in the barrier-wait shadow.

// Scratch: per-step input currents inp_cur[t][n] = input_signal[t,:] @ input_weights[:,n]
__device__ float g_inp_cur[Tn * Nn];

// ---------------------------------------------------------------------------
// Kernel A: tiny GEMM (1000x64 @ 64x128) -> g_inp_cur. Negligible cost.
// ---------------------------------------------------------------------------
__global__ void inp_cur_kernel(const float* __restrict__ sig,
                               const float* __restrict__ w_in) {
    int t = blockIdx.x;
    int n = threadIdx.x;
    float acc = 0.f;
#pragma unroll
    for (int d = 0; d < Dd; ++d)
        acc += sig[t * Dd + d] * w_in[d * Nn + n];
    g_inp_cur[t * Nn + n] = acc;
}

// ---------------------------------------------------------------------------
// Kernel B: 2-warps-per-row SNN simulation (the 809us champion structure).
//   - Warp pair (2r, 2r+1) owns row r; warp half h owns neurons [64h, 64h+64).
//   - Lane l owns neurons 64h + 2l, 64h + 2l + 1 (float2 state in registers).
//   - W_rec (128x128 fp32 = 64KB) in dynamic SMEM, shared by all 8 warps.
//   - rec_t = trace_t @ W maintained incrementally via sparse spike masks:
//       rec = 0.95*rec + sum_{k in spikes} W[k][my 64 cols]
//   - Spike masks exchanged between the two warps of a row through static
//     SMEM, double-buffered by (t&1), one named barrier per row pair.
//   - History stores issue BEFORE the barrier -> STGs drain in barrier shadow.
// ---------------------------------------------------------------------------
__global__ __launch_bounds__(THREADS, 2)
void sim_kernel(const float* __restrict__ Wrec, float* __restrict__ out) {
    extern __shared__ float sW[];                 // Nn*Nn floats = 64KB
    __shared__ unsigned smask[2][8][2];           // [buf][warp][word]

    const int tid = threadIdx.x;
    // Cooperative vectorized load of W_rec into SMEM
    {
        const float4* src = reinterpret_cast<const float4*>(Wrec);
        float4* dst = reinterpret_cast<float4*>(sW);
        for (int i = tid; i < (Nn * Nn) / 4; i += THREADS) dst[i] = src[i];
    }
    __syncthreads();

    const int warp = tid >> 5;
    const int lane = tid & 31;
    const int rloc = warp >> 1;        // row within CTA (0..3)
    const int half = warp & 1;         // which 64-neuron half this warp owns
    const int row = blockIdx.x * ROWS_PER_CTA + rloc;   // 0..999 (exact)
    const int colv = half * 32 + lane; // float2 column index within the row
    const int barid = rloc + 1;        // named barrier per row pair
    const int peer = warp ^ 1;

    float2* __restrict__ out_spk =
        reinterpret_cast<float2*>(out + (size_t)row * Tn * Nn);
    float2* __restrict__ out_mem =
        reinterpret_cast<float2*>(out + (size_t)Bb * Tn * Nn + (size_t)row * Tn * Nn);
    float2* __restrict__ out_trc =
        reinterpret_cast<float2*>(out + (size_t)2 * Bb * Tn * Nn + (size_t)row * Nn);

    const float2* __restrict__ sW2 = reinterpret_cast<const float2*>(sW);

    float2 mem  = {0.f, 0.f};
    float2 syn  = {0.f, 0.f};
    float2 refr = {0.f, 0.f};
    float2 rec  = {0.f, 0.f};   // = trace_{t-1} @ W (incremental), my 2 cols
    float2 trc  = {0.f, 0.f};

    const float2* __restrict__ xin2 = reinterpret_cast<const float2*>(g_inp_cur);
    float2 x = xin2[colv];      // t = 0 input current (my 2 cols)

    for (int t = 0; t < Tn; ++t) {
        // Prefetch next step's input current (L2-resident, shared by all rows)
        const int tnext = (t + 1 < Tn) ? (t + 1) : (Tn - 1);
        const float2 xnext = xin2[tnext * (Nn / 2) + colv];

        // ---- Update my 2 neurons ----
        syn.x = syn.x * 0.8f + x.x + rec.x;
        syn.y = syn.y * 0.8f + x.y + rec.y;
        mem.x = mem.x * 0.9f + syn.x * 0.1f;
        mem.y = mem.y * 0.9f + syn.y * 0.1f;
        mem.x = (refr.x > 0.f) ? 0.f : mem.x;
        mem.y = (refr.y > 0.f) ? 0.f : mem.y;
        refr.x = fmaxf(refr.x - 1.f, 0.f);
        refr.y = fmaxf(refr.y - 1.f, 0.f);
        const bool k0 = mem.x > 1.0f;
        const bool k1 = mem.y > 1.0f;
        const float s0 = k0 ? 1.f : 0.f;
        const float s1 = k1 ? 1.f : 0.f;
        mem.x = k0 ? 0.f : mem.x;
        mem.y = k1 ? 0.f : mem.y;
        refr.x += s0 * 2.f;
        refr.y += s1 * 2.f;
        trc.x = trc.x * 0.95f + s0;
        trc.y = trc.y * 0.95f + s1;

        // ---- Publish spike masks (pre-barrier) ----
        // bit l of word j  <->  neuron 64*half + 2l + j
        const unsigned m0 = __ballot_sync(0xFFFFFFFFu, k0);
        const unsigned m1 = __ballot_sync(0xFFFFFFFFu, k1);
        const int buf = t & 1;
        if (lane == 0) {
            smask[buf][warp][0] = m0;
            smask[buf][warp][1] = m1;
        }

        // ---- History stores BEFORE the barrier: STGs drain in its shadow ----
        out_spk[t * (Nn / 2) + colv] = make_float2(s0, s1);
        out_mem[t * (Nn / 2) + colv] = mem;

        asm volatile("bar.sync %0, 64;" :: "r"(barid) : "memory");
        const unsigned p0 = smask[buf][peer][0];
        const unsigned p1 = smask[buf][peer][1];

        // ---- Incremental recurrent update over 4 spike-mask words ----
        float ax = 0.f, ay = 0.f;
        const int bo = half * 64;        // my warp's neuron base
        const int bp = bo ^ 64;          // peer warp's neuron base
        unsigned m;
        m = m0;
        while (m) { int l = __ffs(m) - 1; m &= m - 1;
            const float2 w = sW2[(bo + 2 * l)     * (Nn / 2) + colv]; ax += w.x; ay += w.y; }
        m = m1;
        while (m) { int l = __ffs(m) - 1; m &= m - 1;
            const float2 w = sW2[(bo + 2 * l + 1) * (Nn / 2) + colv]; ax += w.x; ay += w.y; }
        m = p0;
        while (m) { int l = __ffs(m) - 1; m &= m - 1;
            const float2 w = sW2[(bp + 2 * l)     * (Nn / 2) + colv]; ax += w.x; ay += w.y; }
        m = p1;
        while (m) { int l = __ffs(m) - 1; m &= m - 1;
            const float2 w = sW2[(bp + 2 * l + 1) * (Nn / 2) + colv]; ax += w.x; ay += w.y; }

        rec.x = rec.x * 0.95f + ax;
        rec.y = rec.y * 0.95f + ay;

        x = xnext;
    }

    // Final trace output (B, N)
    out_trc[colv] = trc;
}

// ---------------------------------------------------------------------------
// Harness entry
// ---------------------------------------------------------------------------
extern "C" void kernel_launch(void* const* d_in, const int* in_sizes, int n_in,
                              void* d_out, int out_size) {
    const float* sig   = (const float*)d_in[0];  // (1000, 64)
    const float* w_in  = (const float*)d_in[1];  // (64, 128)
    const float* w_rec = (const float*)d_in[2];  // (128, 128)
    float* out = (float*)d_out;
    (void)in_sizes; (void)n_in; (void)out_size;

    cudaFuncSetAttribute(sim_kernel, cudaFuncAttributeMaxDynamicSharedMemorySize,
                         Nn * Nn * (int)sizeof(float));

    inp_cur_kernel<<<Tn, Nn>>>(sig, w_in);
    sim_kernel<<<Bb / ROWS_PER_CTA, THREADS,
                 Nn * Nn * (int)sizeof(float)>>>(w_rec, out);
}

// round 16
// speedup vs baseline: 1.4678x; 1.1402x over previous
#include <cuda_runtime.h>

typedef unsigned long long ull;

// Problem constants
constexpr int Tn = 1000, Dd = 64, Nn = 128, Bb = 1000;
constexpr int CS = 100;               // sim steps per chunk
constexpr int NCHUNK = Tn / CS;       // 10
constexpr int GRID = 148;             // 1 CTA per SM
constexpr int TPB = 256;
constexpr size_t ROWF = (size_t)Tn * Nn;
constexpr size_t REGION = (size_t)Bb * ROWF;

// KEY INSIGHT 1: reference broadcasts x_t across all B rows from identical
// zero state => all rows identical. Simulate once; broadcast.
// KEY INSIGHT 2 (R16): overlap sim & broadcast via CHUNKED KERNELS: kernel k
// sims chunk k on CTA0 while CTAs 1-147 broadcast chunk k-1. Kernel-boundary
// ordering => zero fences/polling. Sim spike loop: parallel index extraction
// (popc-prefix + fns) + shfl-broadcast walk, no serial ffs chain.

__device__ float g_inp_cur[Tn * Nn];
__device__ float g_spk[Tn * Nn];      // compact spikes (T, N)
__device__ float g_memh[Tn * Nn];     // compact membrane (T, N)
__device__ float g_trc[Nn];           // final trace (N)
// Sim state carried across chunks (lane-indexed float4)
__device__ float4 g_s_syn[32], g_s_mem[32], g_s_refr[32], g_s_rec[32], g_s_trc[32];

// ---------------------------------------------------------------------------
// Kernel A: input currents (1000x64 @ 64x128). ~5us.
// ---------------------------------------------------------------------------
__global__ void inp_cur_kernel(const float* __restrict__ sig,
                               const float* __restrict__ w_in) {
    int t = blockIdx.x, n = threadIdx.x;
    float acc = 0.f;
#pragma unroll
    for (int d = 0; d < Dd; ++d) acc += sig[t * Dd + d] * w_in[d * Nn + n];
    g_inp_cur[t * Nn + n] = acc;
}

__device__ __forceinline__ void fadd2(ull& acc, ull w) {
    asm("add.rn.f32x2 %0, %0, %1;" : "+l"(acc) : "l"(w));
}
__device__ __forceinline__ int fns_bit(unsigned mask, int rank1) {  // 1-based
    int d;
    asm("fns.b32 %0, %1, %2, %3;" : "=r"(d) : "r"(mask), "r"(0), "r"(rank1));
    return d;
}

// ---------------------------------------------------------------------------
// Single-warp sim of CS steps (lane owns neurons 4l..4l+3).
// Spike accumulate: lane i extracts the i-th spike index in parallel
// (popc prefix + fns), then a pipelined shfl+LDS.128+f32x2 loop.
// ---------------------------------------------------------------------------
__device__ void run_sim_chunk(const float* __restrict__ sW, int chunk) {
    const int lane = threadIdx.x;     // 0..31
    float syn[4], mem[4], refr[4], rec[4], trc[4];
    if (chunk == 0) {
#pragma unroll
        for (int j = 0; j < 4; ++j) { syn[j]=mem[j]=refr[j]=rec[j]=trc[j]=0.f; }
    } else {
        const float4 a = g_s_syn[lane], b = g_s_mem[lane], c = g_s_refr[lane],
                     d = g_s_rec[lane], e = g_s_trc[lane];
        syn[0]=a.x; syn[1]=a.y; syn[2]=a.z; syn[3]=a.w;
        mem[0]=b.x; mem[1]=b.y; mem[2]=b.z; mem[3]=b.w;
        refr[0]=c.x; refr[1]=c.y; refr[2]=c.z; refr[3]=c.w;
        rec[0]=d.x; rec[1]=d.y; rec[2]=d.z; rec[3]=d.w;
        trc[0]=e.x; trc[1]=e.y; trc[2]=e.z; trc[3]=e.w;
    }

    const float4* __restrict__ xin = reinterpret_cast<const float4*>(g_inp_cur);
    float4* __restrict__ ospk = reinterpret_cast<float4*>(g_spk);
    float4* __restrict__ omem = reinterpret_cast<float4*>(g_memh);
    const ulonglong2* __restrict__ sWu =
        reinterpret_cast<const ulonglong2*>(sW);   // row k: sWu[k*32 + lane]

    const int t0 = chunk * CS, t1 = t0 + CS;
    float4 x = __ldg(&xin[t0 * 32 + lane]);

    for (int t = t0; t < t1; ++t) {
        const int tn = (t + 1 < Tn) ? (t + 1) : t;
        const float4 xn = __ldg(&xin[tn * 32 + lane]);
        const float xv[4] = {x.x, x.y, x.z, x.w};

        float s[4]; bool kk[4];
#pragma unroll
        for (int j = 0; j < 4; ++j) {
            syn[j] = syn[j] * 0.8f + (xv[j] + rec[j]);
            mem[j] = mem[j] * 0.9f + syn[j] * 0.1f;
            mem[j] = (refr[j] > 0.f) ? 0.f : mem[j];
            refr[j] = fmaxf(refr[j] - 1.f, 0.f);
            kk[j] = mem[j] > 1.0f;
            s[j] = kk[j] ? 1.f : 0.f;
            mem[j] = kk[j] ? 0.f : mem[j];
            refr[j] += s[j] * 2.f;
            trc[j] = trc[j] * 0.95f + s[j];
        }

        unsigned msk[4];
#pragma unroll
        for (int j = 0; j < 4; ++j) msk[j] = __ballot_sync(0xFFFFFFFFu, kk[j]);

        ospk[t * 32 + lane] = make_float4(s[0], s[1], s[2], s[3]);
        omem[t * 32 + lane] = make_float4(mem[0], mem[1], mem[2], mem[3]);

        // ---- parallel spike-index extraction + pipelined accumulate ----
        const int p0 = __popc(msk[0]);
        const int p1 = p0 + __popc(msk[1]);
        const int p2 = p1 + __popc(msk[2]);
        const int S  = p2 + __popc(msk[3]);

        ull aA0 = 0, aA1 = 0, aB0 = 0, aB1 = 0;
        for (int base = 0; base < S; base += 32) {
            const int i = base + lane;
            // word j and rank r of the i-th spike (branchless selects)
            const int j = (i < p0) ? 0 : (i < p1) ? 1 : (i < p2) ? 2 : 3;
            const int r = (i < p0) ? i : (i < p1) ? i - p0
                         : (i < p2) ? i - p1 : i - p2;
            const unsigned mj = msk[j];
            const int bit = fns_bit(mj, r + 1);
            const int myidx = (i < S) ? (4 * bit + j) : 128;  // 128 = zero row

            const int cnt = (S - base < 32) ? (S - base) : 32;
            const int cntp = (cnt + 1) & ~1;
            for (int q = 0; q < cntp; q += 2) {
                const int k0 = __shfl_sync(0xFFFFFFFFu, myidx, q);
                const int k1 = __shfl_sync(0xFFFFFFFFu, myidx, q + 1);
                const ulonglong2 w0 = sWu[k0 * 32 + lane];
                const ulonglong2 w1 = sWu[k1 * 32 + lane];
                fadd2(aA0, w0.x); fadd2(aA1, w0.y);
                fadd2(aB0, w1.x); fadd2(aB1, w1.y);
            }
        }
        fadd2(aA0, aB0); fadd2(aA1, aB1);

        rec[0] = rec[0] * 0.95f + __int_as_float((int)aA0);
        rec[1] = rec[1] * 0.95f + __int_as_float((int)(aA0 >> 32));
        rec[2] = rec[2] * 0.95f + __int_as_float((int)aA1);
        rec[3] = rec[3] * 0.95f + __int_as_float((int)(aA1 >> 32));

        x = xn;
    }

    // Save state for next chunk (always; deterministic under graph replay)
    g_s_syn[lane]  = make_float4(syn[0], syn[1], syn[2], syn[3]);
    g_s_mem[lane]  = make_float4(mem[0], mem[1], mem[2], mem[3]);
    g_s_refr[lane] = make_float4(refr[0], refr[1], refr[2], refr[3]);
    g_s_rec[lane]  = make_float4(rec[0], rec[1], rec[2], rec[3]);
    g_s_trc[lane]  = make_float4(trc[0], trc[1], trc[2], trc[3]);
    if (chunk == NCHUNK - 1)
        reinterpret_cast<float4*>(g_trc)[lane] =
            make_float4(trc[0], trc[1], trc[2], trc[3]);
}

// ---------------------------------------------------------------------------
// Broadcast chunk ck: 2000 (row, region) tasks; each = contiguous CS*512B
// copy from the compact buffer (L2-hot) into the destination row.
// ---------------------------------------------------------------------------
__device__ void bcast_chunk(float* __restrict__ out, int ck, int w, int nw,
                            int tid) {
    const int t0 = ck * CS;
    const float4* __restrict__ sspk =
        reinterpret_cast<const float4*>(g_spk) + t0 * 32;
    const float4* __restrict__ smem =
        reinterpret_cast<const float4*>(g_memh) + t0 * 32;
    float4* __restrict__ out4 = reinterpret_cast<float4*>(out);

    for (int tau = w; tau < 2 * Bb; tau += nw) {
        const int region = (tau >= Bb) ? 1 : 0;
        const int row = tau - region * Bb;
        const float4* __restrict__ src = region ? smem : sspk;
        float4* __restrict__ dst = out4 + (size_t)region * (REGION / 4) +
                                   (size_t)row * (ROWF / 4) + (size_t)t0 * 32;
        for (int i = tid; i < CS * 32; i += TPB)
            __stcs(&dst[i], __ldg(&src[i]));
    }
}

// ---------------------------------------------------------------------------
// Pipeline kernel k: CTA0 sims chunk k; CTAs 1..147 broadcast chunk k-1.
// ---------------------------------------------------------------------------
__global__ __launch_bounds__(TPB, 1)
void pipe_kernel(const float* __restrict__ Wrec, float* __restrict__ out,
                 int chunk) {
    extern __shared__ float sW[];   // 129*128 floats; row 128 = zeros
    const int bid = blockIdx.x, tid = threadIdx.x;

    if (bid == 0) {
        for (int i = tid; i < (129 * Nn) / 4; i += TPB)
            reinterpret_cast<float4*>(sW)[i] =
                (i < (Nn * Nn) / 4) ? reinterpret_cast<const float4*>(Wrec)[i]
                                    : make_float4(0.f, 0.f, 0.f, 0.f);
        __syncthreads();
        if (tid < 32) run_sim_chunk(sW, chunk);
        return;
    }
    if (chunk > 0) bcast_chunk(out, chunk - 1, bid - 1, GRID - 1, tid);
}

// ---------------------------------------------------------------------------
// Final kernel: broadcast last chunk + trace rows.
// ---------------------------------------------------------------------------
__global__ __launch_bounds__(TPB, 1)
void final_kernel(float* __restrict__ out) {
    const int bid = blockIdx.x, tid = threadIdx.x;
    bcast_chunk(out, NCHUNK - 1, bid, GRID, tid);
    // trace: (B, N) rows
    if (tid < 32) {
        const float4 v = __ldg(&reinterpret_cast<const float4*>(g_trc)[tid]);
        float4* __restrict__ out4 = reinterpret_cast<float4*>(out);
        for (int r = bid; r < Bb; r += GRID)
            __stcs(&out4[2 * (REGION / 4) + (size_t)r * 32 + tid], v);
    }
}

// ---------------------------------------------------------------------------
// Harness entry
// ---------------------------------------------------------------------------
extern "C" void kernel_launch(void* const* d_in, const int* in_sizes, int n_in,
                              void* d_out, int out_size) {
    const float* sig   = (const float*)d_in[0];  // (1000, 64)
    const float* w_in  = (const float*)d_in[1];  // (64, 128)
    const float* w_rec = (const float*)d_in[2];  // (128, 128)
    float* out = (float*)d_out;
    (void)in_sizes; (void)n_in; (void)out_size;

    const int smem = 129 * Nn * (int)sizeof(float);  // 66048 B
    cudaFuncSetAttribute(pipe_kernel,
                         cudaFuncAttributeMaxDynamicSharedMemorySize, smem);

    inp_cur_kernel<<<Tn, Nn>>>(sig, w_in);
    for (int k = 0; k < NCHUNK; ++k)
        pipe_kernel<<<GRID, TPB, smem>>>(w_rec, out, k);
    final_kernel<<<GRID, TPB>>>(out);
}